// round 1
// baseline (speedup 1.0000x reference)
#include <cuda_runtime.h>
#include <math.h>

// Problem constants
#define B_   32
#define H_   14
#define W_   14
#define C_   32
#define K_   64
#define KS_  5
#define OH_  10
#define P_   100          // OH*OW
#define N_   196          // H*W
#define M_   800          // KS*KS*C
#define ROWPAD 34         // smem row stride for [pos][c] tiles (pad 32 -> 34, even for 8B loads)

#define MU_OUT_ELEMS (B_*P_*K_)          // 204800
#define SIG_OFFSET   MU_OUT_ELEMS

// Scratch (device globals; no allocation allowed)
__device__ float g_diag[B_*N_*C_];       // diag(Sigma_in): [b][n][c]
__device__ float g_diagvals[B_*P_*K_];   // v1 + sp*tr

// ---------- f32x2 packed helpers ----------
typedef unsigned long long ull;

__device__ __forceinline__ ull f2_pack(float x, float y) {
    ull r; asm("mov.b64 %0, {%1,%2};" : "=l"(r) : "f"(x), "f"(y)); return r;
}
__device__ __forceinline__ void f2_fma(ull& d, ull a, ull b) {
    asm("fma.rn.f32x2 %0, %1, %2, %3;" : "=l"(d) : "l"(a), "l"(b), "l"(d));
}
__device__ __forceinline__ ull f2_mul(ull a, ull b) {
    ull d; asm("mul.rn.f32x2 %0, %1, %2;" : "=l"(d) : "l"(a), "l"(b)); return d;
}
__device__ __forceinline__ ull f2_add(ull a, ull b) {
    ull d; asm("add.rn.f32x2 %0, %1, %2;" : "=l"(d) : "l"(a), "l"(b)); return d;
}
__device__ __forceinline__ float2 f2_unpack(ull v) {
    float x, y; asm("mov.b64 {%0,%1}, %2;" : "=f"(x), "=f"(y) : "l"(v));
    return make_float2(x, y);
}

// =====================================================================
// Kernel 0: gather diag of Sigma_in  ->  g_diag[b][n][c]
// 32*196*8 float4 = 50176 threads
// =====================================================================
__global__ void k0_diag(const float* __restrict__ Sigma) {
    int t = blockIdx.x * blockDim.x + threadIdx.x;  // grid 196 x 256 = exactly 50176
    int c4 = t & 7;
    int n  = (t >> 3) % N_;
    int b  = t / (N_ * 8);
    size_t src = ((size_t)(b * N_ + n) * N_ + n) * C_ + c4 * 4;
    float4 v = *reinterpret_cast<const float4*>(Sigma + src);
    *reinterpret_cast<float4*>(&g_diag[(b * N_ + n) * C_ + c4 * 4]) = v;
}

// =====================================================================
// Kernel 1: both conv paths.
//   mu_out[b,p,k]    = sum_m A[p,m] * w[m,k]
//   diagvals[b,p,k]  = sum_m D[p,m] * w[m,k]^2 + sp[k]*sum_m D[p,m]
// grid (5 p-tiles of 20, 32 batches), blockDim 160.
// Thread org: 4 c-groups (8 channels each) x (5 tp x 8 tk).
// Thread tile: r_p=4 (p), r_k=8 (k as 4 f32x2 pairs). Smem reduce over groups.
// Dynamic smem: mu_s[196*34] + ds_s[196*34] + w_s[5*32*64] + tr[80] = 94592 B
// =====================================================================
extern "C" __global__ void __launch_bounds__(160, 1)
k1_conv(const float* __restrict__ mu_in, const float* __restrict__ w_mu,
        const float* __restrict__ w_sigma, float* __restrict__ out_base) {
    extern __shared__ float smem[];
    float* mu_s = smem;                 // 6664
    float* ds_s = smem + 6664;          // 6664
    float* w_s  = smem + 13328;         // 10240 (also reused as reduction buffer)
    float* trb  = smem + 23568;         // 80

    const int b     = blockIdx.y;
    const int pbase = blockIdx.x * 20;
    const int tid   = threadIdx.x;
    const int g     = tid / 40;         // c-group 0..3
    const int w40   = tid % 40;
    const int tp    = w40 / 8;          // 0..4
    const int tk    = w40 % 8;          // 0..7
    const int kbase = tk * 8;

    // load mu_in[b] and g_diag[b] into padded smem
    const float* mu_b = mu_in + b * (N_ * C_);
    const float* dg_b = g_diag + b * (N_ * C_);
    for (int idx = tid; idx < N_ * C_; idx += 160) {
        int pos = idx >> 5, c = idx & 31;
        mu_s[pos * ROWPAD + c] = mu_b[idx];
        ds_s[pos * ROWPAD + c] = dg_b[idx];
    }

    int prc[4];
#pragma unroll
    for (int r = 0; r < 4; ++r) {
        int p = pbase + tp * 4 + r;
        prc[r] = (p / OH_) * W_ + (p % OH_);
    }

    ull accA[4][4], accV[4][4];
#pragma unroll
    for (int r = 0; r < 4; ++r)
#pragma unroll
        for (int kk = 0; kk < 4; ++kk) { accA[r][kk] = 0ull; accV[r][kk] = 0ull; }
    float trp[4] = {0.f, 0.f, 0.f, 0.f};

    for (int chunk = 0; chunk < 5; ++chunk) {
        __syncthreads();
        const float* wg = w_mu + chunk * (5 * C_ * K_);
        for (int idx = tid; idx < 2560; idx += 160) {
            float4 v = *reinterpret_cast<const float4*>(wg + idx * 4);
            *reinterpret_cast<float4*>(&w_s[idx * 4]) = v;
        }
        __syncthreads();

        for (int ijl = 0; ijl < 5; ++ijl) {
            int ij = chunk * 5 + ijl;
            int ijoff = (ij / KS_) * W_ + (ij % KS_);
            int ao[4];
#pragma unroll
            for (int r = 0; r < 4; ++r) ao[r] = (prc[r] + ijoff) * ROWPAD + g * 8;
            int wbase = (ijl * C_ + g * 8) * K_ + kbase;

#pragma unroll
            for (int cc = 0; cc < 8; ++cc) {
                float a[4], d[4];
#pragma unroll
                for (int r = 0; r < 4; ++r) {
                    a[r] = mu_s[ao[r] + cc];
                    d[r] = ds_s[ao[r] + cc];
                }
                const ull* wp = reinterpret_cast<const ull*>(&w_s[wbase + cc * K_]);
                ull wv[4], w2[4];
#pragma unroll
                for (int kk = 0; kk < 4; ++kk) { wv[kk] = wp[kk]; w2[kk] = f2_mul(wv[kk], wv[kk]); }
#pragma unroll
                for (int r = 0; r < 4; ++r) {
                    ull aa = f2_pack(a[r], a[r]);
                    ull dd = f2_pack(d[r], d[r]);
#pragma unroll
                    for (int kk = 0; kk < 4; ++kk) {
                        f2_fma(accA[r][kk], aa, wv[kk]);
                        f2_fma(accV[r][kk], dd, w2[kk]);
                    }
                }
                if (tk == 0) {
#pragma unroll
                    for (int r = 0; r < 4; ++r) trp[r] += d[r];
                }
            }
        }
    }

    // cross-group reduction through smem (reuse w_s)
    __syncthreads();
    ull* redu = reinterpret_cast<ull*>(w_s);
    if (tk == 0) {
#pragma unroll
        for (int r = 0; r < 4; ++r) trb[g * 20 + tp * 4 + r] = trp[r];
    }
    if (g > 0) {
        ull* dst = redu + ((g - 1) * 40 + w40) * 32;
#pragma unroll
        for (int r = 0; r < 4; ++r)
#pragma unroll
            for (int kk = 0; kk < 4; ++kk) {
                dst[r * 4 + kk]      = accA[r][kk];
                dst[16 + r * 4 + kk] = accV[r][kk];
            }
    }
    __syncthreads();

    if (g == 0) {
#pragma unroll
        for (int gg = 1; gg < 4; ++gg) {
            const ull* src = redu + ((gg - 1) * 40 + w40) * 32;
#pragma unroll
            for (int r = 0; r < 4; ++r)
#pragma unroll
                for (int kk = 0; kk < 4; ++kk) {
                    accA[r][kk] = f2_add(accA[r][kk], src[r * 4 + kk]);
                    accV[r][kk] = f2_add(accV[r][kk], src[16 + r * 4 + kk]);
                }
        }
        float sp8[8];
#pragma unroll
        for (int q = 0; q < 8; ++q) sp8[q] = log1pf(expf(w_sigma[kbase + q]));

        float* mu_out = out_base;  // first region of d_out
#pragma unroll
        for (int r = 0; r < 4; ++r) {
            float trt = trb[tp * 4 + r] + trb[20 + tp * 4 + r] +
                        trb[40 + tp * 4 + r] + trb[60 + tp * 4 + r];
            int p  = pbase + tp * 4 + r;
            int ob = (b * P_ + p) * K_ + kbase;
#pragma unroll
            for (int kk = 0; kk < 4; ++kk) {
                float2 ma = f2_unpack(accA[r][kk]);
                *reinterpret_cast<float2*>(&mu_out[ob + kk * 2]) = ma;
                float2 mv = f2_unpack(accV[r][kk]);
                float2 dv = make_float2(mv.x + sp8[kk * 2] * trt,
                                        mv.y + sp8[kk * 2 + 1] * trt);
                *reinterpret_cast<float2*>(&g_diagvals[ob + kk * 2]) = dv;
            }
        }
    }
}

// =====================================================================
// Kernel 2: G = mu_p * mu_p^T  fused with Sigma_out epilogue.
// grid (10 p-tiles of 10, 32 batches), blockDim 160.
// Thread org: 4 c-groups x (2 tp x 20 tq), thread tile 5(p) x 5(q),
// packed over the reduction dim (c pairs). Smem reduce, then stream writes.
// Static smem: mu_s 6664 + gbuf 4000 + sp 64 = 42912 B
// =====================================================================
extern "C" __global__ void __launch_bounds__(160, 2)
k2_sigma(const float* __restrict__ mu_in, const float* __restrict__ w_sigma,
         float* __restrict__ out_base) {
    __shared__ float mu_s[N_ * ROWPAD];   // 6664
    __shared__ float gbuf[4 * 1000];
    __shared__ float sp_s[K_];

    const int b   = blockIdx.y;
    const int p0  = blockIdx.x * 10;
    const int tid = threadIdx.x;
    const int g   = tid / 40;
    const int w40 = tid % 40;
    const int tp  = w40 / 20;   // 0..1
    const int tq  = w40 % 20;   // 0..19

    const float* mu_b = mu_in + b * (N_ * C_);
    for (int idx = tid; idx < N_ * C_; idx += 160) {
        int pos = idx >> 5, c = idx & 31;
        mu_s[pos * ROWPAD + c] = mu_b[idx];
    }
    if (tid < K_) sp_s[tid] = log1pf(expf(w_sigma[tid]));
    __syncthreads();

    int prc[5], qrc[5];
#pragma unroll
    for (int r = 0; r < 5; ++r) {
        int p = p0 + tp * 5 + r;
        prc[r] = (p / OH_) * W_ + (p % OH_);
        int q = tq * 5 + r;
        qrc[r] = (q / OH_) * W_ + (q % OH_);
    }

    ull acc[25];
#pragma unroll
    for (int i = 0; i < 25; ++i) acc[i] = 0ull;

    for (int ij = 0; ij < 25; ++ij) {
        int ijoff = (ij / KS_) * W_ + (ij % KS_);
        int ao[5], bo[5];
#pragma unroll
        for (int r = 0; r < 5; ++r) {
            ao[r] = (prc[r] + ijoff) * ROWPAD + g * 8;
            bo[r] = (qrc[r] + ijoff) * ROWPAD + g * 8;
        }
#pragma unroll
        for (int c2 = 0; c2 < 4; ++c2) {
            int o2 = c2 * 2;
            ull a2[5], b2[5];
#pragma unroll
            for (int r = 0; r < 5; ++r) {
                a2[r] = *reinterpret_cast<const ull*>(&mu_s[ao[r] + o2]);
                b2[r] = *reinterpret_cast<const ull*>(&mu_s[bo[r] + o2]);
            }
#pragma unroll
            for (int r = 0; r < 5; ++r)
#pragma unroll
                for (int s = 0; s < 5; ++s)
                    f2_fma(acc[r * 5 + s], a2[r], b2[s]);
        }
    }

    // horizontal sum + per-group partials into smem
#pragma unroll
    for (int r = 0; r < 5; ++r)
#pragma unroll
        for (int s = 0; s < 5; ++s) {
            float2 v = f2_unpack(acc[r * 5 + s]);
            gbuf[g * 1000 + (tp * 5 + r) * 100 + tq * 5 + s] = v.x + v.y;
        }
    __syncthreads();

    for (int idx = tid; idx < 1000; idx += 160) {
        float gv = gbuf[idx] + gbuf[1000 + idx] + gbuf[2000 + idx] + gbuf[3000 + idx];
        gbuf[idx] = gv;
    }
    __syncthreads();

    // epilogue: Sigma_out[b, p0+pp, q, k] = sp[k]*G + (p==q)*diagvals, abs on q==k
    float* sig_out = out_base + SIG_OFFSET;
    for (int idx = tid; idx < 16000; idx += 160) {   // 10*100*16 float4
        int k4 = idx & 15;
        int q  = (idx >> 4) % P_;
        int pp = idx / 1600;
        float gv = gbuf[pp * 100 + q];
        const float4 sv = *reinterpret_cast<const float4*>(&sp_s[k4 * 4]);
        float4 o;
        o.x = sv.x * gv; o.y = sv.y * gv; o.z = sv.z * gv; o.w = sv.w * gv;
        int p = p0 + pp;
        if (p == q) {
            const float4 dv = *reinterpret_cast<const float4*>(
                &g_diagvals[(b * P_ + p) * K_ + k4 * 4]);
            o.x += dv.x; o.y += dv.y; o.z += dv.z; o.w += dv.w;
        }
        int kb = k4 * 4;
        if (q == kb + 0) o.x = fabsf(o.x);
        if (q == kb + 1) o.y = fabsf(o.y);
        if (q == kb + 2) o.z = fabsf(o.z);
        if (q == kb + 3) o.w = fabsf(o.w);
        *reinterpret_cast<float4*>(
            &sig_out[((b * P_ + p) * P_ + q) * K_ + kb]) = o;
    }
}

// =====================================================================
// Launch
// =====================================================================
extern "C" void kernel_launch(void* const* d_in, const int* in_sizes, int n_in,
                              void* d_out, int out_size) {
    const float* mu_in    = (const float*)d_in[0];
    const float* Sigma_in = (const float*)d_in[1];
    const float* w_mu     = (const float*)d_in[2];
    const float* w_sigma  = (const float*)d_in[3];
    float* out = (float*)d_out;

    cudaFuncSetAttribute(k1_conv, cudaFuncAttributeMaxDynamicSharedMemorySize, 94592);

    k0_diag<<<196, 256>>>(Sigma_in);
    k1_conv<<<dim3(5, 32), 160, 94592>>>(mu_in, w_mu, w_sigma, out);
    k2_sigma<<<dim3(10, 32), 160>>>(mu_in, w_sigma, out);
}